// round 7
// baseline (speedup 1.0000x reference)
#include <cuda_runtime.h>
#include <cuda_fp16.h>
#include <cstdint>

#define R_TOT 1152
#define B_TOT 256
#define C_N 10
#define O_N 16
#define CO 160
#define I_N 8

// kroute tiling
#define NCH_R 8            // route chunks per batch
#define RCHK 144           // rows per route chunk
#define PAD_H 170          // fp16 row stride (340B, odd halves -> conflict-free)
#define TILE_H (RCHK * PAD_H)          // 24480 halves
#define TILE_BYTES (TILE_H * 2)        // 48960 (16B multiple)

// k1 tiling
#define TB 16              // batches per k1 block
#define K1_RC 36           // rows per k1 block
#define K1_NCH 32          // 1152/36 r-chunks
#define K1_PARTS 64        // s1 partial chunks (2 groups per block)

// Scratch (device globals: allocation-free kernel_launch)
__device__ __half g_uh[(size_t)B_TOT * NCH_R * TILE_H];      // ~100 MB fp16 (fits L2)
__device__ float  g_b2[(size_t)B_TOT * R_TOT * C_N];         // b after iter-1 update
__device__ float  g_spart1[(size_t)K1_PARTS * B_TOT * CO];   // k1 partial s
__device__ float  g_spart2[2][(size_t)NCH_R * B_TOT * CO];   // kroute partial s
__device__ int    g_cnt[B_TOT];                              // last-block counters

__device__ __forceinline__ uint32_t smem_u32(const void* p) {
    uint32_t a;
    asm("{ .reg .u64 t; cvta.to.shared.u64 t, %1; cvt.u32.u64 %0, t; }" : "=r"(a) : "l"(p));
    return a;
}

// ---------------------------------------------------------------------------
// K1: u_hat -> fp16 padded tiles, fused softmax(b_init) + s1 partials.
// grid = 16 b-tiles x 32 r-chunks = 512 blocks, 160 threads.
// LSU-optimized: 2 co-columns per thread (80 threads cover 160 cols; the two
// 80-thread groups split the 36 rows), half2 stores, coefficient tile
// transposed to [rr][c][bb] so 16 per-bb scalars load as 4x LDS.128.
// ---------------------------------------------------------------------------
__global__ __launch_bounds__(160) void k1(const float* __restrict__ x,
                                          const float* __restrict__ W,
                                          const float* __restrict__ binit) {
    const int bt = blockIdx.x & 15;
    const int rc = blockIdx.x >> 4;          // 0..31 (36-row chunk)
    const int b0 = bt * TB;
    const int tid = threadIdx.x;
    const int r0 = rc * K1_RC;
    const int chk_g = rc >> 2;               // 144-row tile id
    const int rin0 = (rc & 3) * K1_RC;       // row offset within tile

    const int grp = tid / 80;                // rr half: 0 or 1
    const int u   = tid - grp * 80;          // half2 column 0..79 (cols 2u, 2u+1)
    const int c   = u >> 3;                  // capsule (shared by both cols)

    __shared__ float x_sm[TB][K1_RC][I_N];
    __shared__ float c_smT[K1_RC][C_N][TB];  // transposed: bb fastest

    const float4* W4 = reinterpret_cast<const float4*>(W);
    const float4* x4 = reinterpret_cast<const float4*>(x);

    // stage x tile (float4-coalesced): TB*K1_RC*8 floats
    for (int i = tid; i < TB * K1_RC * 2; i += 160) {
        int bb = i / (K1_RC * 2);
        int rem = i - bb * (K1_RC * 2);
        reinterpret_cast<float4*>(&x_sm[bb][0][0])[rem] =
            x4[((size_t)(b0 + bb) * R_TOT + r0) * 2 + rem];
    }
    // softmax(b_init) -> transposed coefficient tile
    for (int p = tid; p < TB * K1_RC; p += 160) {
        int bb = p / K1_RC;
        int rr = p - bb * K1_RC;
        const float* bp = binit + ((size_t)(b0 + bb) * R_TOT + r0 + rr) * C_N;
        float e[C_N];
        float m = bp[0];
#pragma unroll
        for (int j = 1; j < C_N; j++) m = fmaxf(m, bp[j]);
        float sum = 0.f;
#pragma unroll
        for (int j = 0; j < C_N; j++) { e[j] = expf(bp[j] - m); sum += e[j]; }
        float inv = 1.f / sum;
#pragma unroll
        for (int j = 0; j < C_N; j++) c_smT[rr][j][bb] = e[j] * inv;
    }
    __syncthreads();

    float2 s_acc[TB];
#pragma unroll
    for (int i = 0; i < TB; i++) s_acc[i] = make_float2(0.f, 0.f);

    for (int rl = 0; rl < K1_RC / 2; rl++) {
        const int rr = grp * (K1_RC / 2) + rl;
        const int r = r0 + rr;
        const int rin = rin0 + rr;
        // W rows for both columns: 4x LDG.128, coalesced
        const float4* wp = W4 + ((size_t)r * CO + 2 * u) * 2;
        const float4 w0a = wp[0], w0b = wp[1];
        const float4 w1a = wp[2], w1b = wp[3];
        // 16 routing coefficients for this (rr, c): 4x LDS.128
        float c16[16];
        {
            const float4* cp = reinterpret_cast<const float4*>(&c_smT[rr][c][0]);
#pragma unroll
            for (int q = 0; q < 4; q++) {
                float4 v = cp[q];
                c16[4 * q] = v.x; c16[4 * q + 1] = v.y;
                c16[4 * q + 2] = v.z; c16[4 * q + 3] = v.w;
            }
        }
        __half2* dst = reinterpret_cast<__half2*>(
            g_uh + ((size_t)b0 * NCH_R + chk_g) * TILE_H + (size_t)rin * PAD_H);
#pragma unroll
        for (int bb = 0; bb < TB; bb++) {
            const float4* xp = reinterpret_cast<const float4*>(&x_sm[bb][rr][0]);
            float4 xa = xp[0], xb = xp[1];
            float uh0 = w0a.x * xa.x + w0a.y * xa.y + w0a.z * xa.z + w0a.w * xa.w
                      + w0b.x * xb.x + w0b.y * xb.y + w0b.z * xb.z + w0b.w * xb.w;
            float uh1 = w1a.x * xa.x + w1a.y * xa.y + w1a.z * xa.z + w1a.w * xa.w
                      + w1b.x * xb.x + w1b.y * xb.y + w1b.z * xb.z + w1b.w * xb.w;
            // one STG.32 per pair
            dst[(size_t)bb * (NCH_R * TILE_H / 2) + u] = __floats2half2_rn(uh0, uh1);
            const float cf = c16[bb];
            s_acc[bb].x = fmaf(cf, uh0, s_acc[bb].x);
            s_acc[bb].y = fmaf(cf, uh1, s_acc[bb].y);
        }
    }
    const int chunk = rc * 2 + grp;
#pragma unroll
    for (int bb = 0; bb < TB; bb++) {
        float2* sp = reinterpret_cast<float2*>(
            g_spart1 + ((size_t)chunk * B_TOT + (b0 + bb)) * CO);
        sp[u] = s_acc[bb];
    }
}

// ---------------------------------------------------------------------------
// Fused routing pass (iter = 2 or 3): bulk-copy 48.96KB fp16 tile, overlap
// with in-block v recompute, then agreement -> b update -> softmax -> partial
// s_next. In iter 3, the last block per batch also does the final squash.
// grid = 256 b x 8 chunks = 2048 blocks, 160 threads.
// ---------------------------------------------------------------------------
__global__ __launch_bounds__(160) void kroute(const float* __restrict__ binit,
                                              float* __restrict__ out, int iter) {
    extern __shared__ __align__(16) char smem_raw[];
    __half* uh = reinterpret_cast<__half*>(smem_raw);             // TILE_H halves
    float* cT  = reinterpret_cast<float*>(smem_raw + TILE_BYTES); // [C_N][RCHK]
    float* vs  = cT + C_N * RCHK;                                 // CO
    __shared__ __align__(8) unsigned long long mbar;
    __shared__ int is_last;

    const int b   = blockIdx.x >> 3;
    const int chk = blockIdx.x & 7;
    const int tid = threadIdx.x;

    const uint32_t uh_s = smem_u32(uh);
    const uint32_t mb_s = smem_u32(&mbar);

    if (tid == 0) {
        asm volatile("mbarrier.init.shared.b64 [%0], 1;" :: "r"(mb_s) : "memory");
        asm volatile("mbarrier.arrive.expect_tx.shared.b64 _, [%0], %1;"
                     :: "r"(mb_s), "r"((uint32_t)TILE_BYTES) : "memory");
        const __half* src = g_uh + ((size_t)b * NCH_R + chk) * TILE_H;
        asm volatile("cp.async.bulk.shared::cta.global.mbarrier::complete_tx::bytes "
                     "[%0], [%1], %2, [%3];"
                     :: "r"(uh_s), "l"(src), "r"((uint32_t)TILE_BYTES), "r"(mb_s)
                     : "memory");
    }

    // Overlap with bulk copy: recompute v = squash(sum of prev partials).
    if (tid < CO) {
        float s = 0.f;
        if (iter == 2) {
#pragma unroll 8
            for (int p = 0; p < K1_PARTS; p++)
                s += g_spart1[((size_t)p * B_TOT + b) * CO + tid];
        } else {
#pragma unroll
            for (int p = 0; p < NCH_R; p++)
                s += g_spart2[0][((size_t)p * B_TOT + b) * CO + tid];
        }
        float n = s * s;
#pragma unroll
        for (int off = 8; off >= 1; off >>= 1)
            n += __shfl_xor_sync(0xffffffffu, n, off);
        float scale = (n / (1.f + n)) * rsqrtf(n + 1e-8f);
        vs[tid] = scale * s;
    }
    __syncthreads();

    // wait for bulk copy (phase 0)
    asm volatile(
        "{\n\t.reg .pred P;\n\t"
        "W_%=: mbarrier.try_wait.parity.shared.b64 P, [%0], 0;\n\t"
        "@!P bra W_%=;\n\t}"
        :: "r"(mb_s) : "memory");

    // Phase A: agreement + b update + softmax. 1 thread per row.
    if (tid < RCHK) {
        const int r = chk * RCHK + tid;
        const float* bin = (iter == 2) ? (binit + ((size_t)b * R_TOT + r) * C_N)
                                       : (g_b2  + ((size_t)b * R_TOT + r) * C_N);
        const __half2* urow = reinterpret_cast<const __half2*>(uh + tid * PAD_H);
        float bv[C_N];
#pragma unroll
        for (int cc = 0; cc < C_N; cc++) {
            float a = 0.f;
#pragma unroll
            for (int k = 0; k < 8; k++) {
                float2 f = __half22float2(urow[cc * 8 + k]);
                a = fmaf(f.x, vs[cc * 16 + 2 * k], a);
                a = fmaf(f.y, vs[cc * 16 + 2 * k + 1], a);
            }
            bv[cc] = bin[cc] + a;
        }
        if (iter == 2) {
            float* bo = g_b2 + ((size_t)b * R_TOT + r) * C_N;
#pragma unroll
            for (int cc = 0; cc < C_N; cc++) bo[cc] = bv[cc];
        }
        float m = bv[0];
#pragma unroll
        for (int cc = 1; cc < C_N; cc++) m = fmaxf(m, bv[cc]);
        float e[C_N], sum = 0.f;
#pragma unroll
        for (int cc = 0; cc < C_N; cc++) { e[cc] = expf(bv[cc] - m); sum += e[cc]; }
        float inv = 1.f / sum;
#pragma unroll
        for (int cc = 0; cc < C_N; cc++) cT[cc * RCHK + tid] = e[cc] * inv;
    }
    __syncthreads();

    // Phase B: s partial; thread = (c,o), loop rows.
    {
        const int cc = tid >> 4;
        const float* crow = cT + cc * RCHK;
        float acc = 0.f;
#pragma unroll 4
        for (int r = 0; r < RCHK; r++)
            acc = fmaf(crow[r], __half2float(uh[r * PAD_H + tid]), acc);
        const int slot = (iter == 2) ? 0 : 1;
        g_spart2[slot][((size_t)chk * B_TOT + b) * CO + tid] = acc;
    }

    // Iter 3: last block per batch performs the final squash -> out.
    if (iter == 3) {
        __threadfence();
        __syncthreads();
        if (tid == 0) {
            int prev = atomicAdd(&g_cnt[b], 1);
            is_last = (prev == NCH_R - 1);
        }
        __syncthreads();
        if (is_last) {
            __threadfence();
            if (tid < CO) {
                float s = 0.f;
#pragma unroll
                for (int p = 0; p < NCH_R; p++)
                    s += g_spart2[1][((size_t)p * B_TOT + b) * CO + tid];
                float n = s * s;
#pragma unroll
                for (int off = 8; off >= 1; off >>= 1)
                    n += __shfl_xor_sync(0xffffffffu, n, off);
                float scale = (n / (1.f + n)) * rsqrtf(n + 1e-8f);
                out[(size_t)b * CO + tid] = scale * s;
            }
            if (tid == 0) g_cnt[b] = 0;   // reset for next graph replay
        }
    }
}

// ---------------------------------------------------------------------------
extern "C" void kernel_launch(void* const* d_in, const int* in_sizes, int n_in,
                              void* d_out, int out_size) {
    const float *x = nullptr, *W = nullptr, *binit = nullptr;
    for (int i = 0; i < n_in; i++) {
        if (in_sizes[i] == B_TOT * R_TOT * I_N)          x     = (const float*)d_in[i];
        else if (in_sizes[i] == R_TOT * C_N * O_N * I_N) W     = (const float*)d_in[i];
        else if (in_sizes[i] == B_TOT * R_TOT * C_N)     binit = (const float*)d_in[i];
    }
    float* out = (float*)d_out;

    const int SMEM_ROUTE = TILE_BYTES + (C_N * RCHK + CO) * (int)sizeof(float);
    cudaFuncSetAttribute(kroute, cudaFuncAttributeMaxDynamicSharedMemorySize, SMEM_ROUTE);

    // iter 1: u_hat (fp16) + s1 partials
    k1<<<512, 160>>>(x, W, binit);
    // iter 2: v1 (in-block) + agreement + b2 + softmax + s2
    kroute<<<2048, 160, SMEM_ROUTE>>>(binit, out, 2);
    // iter 3: v2 (in-block) + agreement + softmax + s3 + fused final squash
    kroute<<<2048, 160, SMEM_ROUTE>>>(binit, out, 3);
}

// round 8
// speedup vs baseline: 1.0684x; 1.0684x over previous
#include <cuda_runtime.h>
#include <cuda_fp16.h>
#include <cstdint>

#define R_TOT 1152
#define B_TOT 256
#define C_N 10
#define O_N 16
#define CO 160
#define I_N 8

// kroute tiling
#define NCH_R 8            // route chunks per batch
#define RCHK 144           // rows per route chunk
#define PAD_H 170          // fp16 row stride (340B, odd halves -> conflict-free)
#define TILE_H (RCHK * PAD_H)          // 24480 halves
#define TILE_BYTES (TILE_H * 2)        // 48960 (16B multiple)

// k1 tiling
#define TB 16              // batches per k1 block
#define K1_RC 18           // rows per k1 block (halved -> 1024 blocks, fills chip)
#define K1_NCH 64          // 1152/18 r-chunks
#define K1_PARTS 64        // s1 partial chunks

// Scratch (device globals: allocation-free kernel_launch)
__device__ __half g_uh[(size_t)B_TOT * NCH_R * TILE_H];      // ~100 MB fp16 (fits L2)
__device__ float  g_b2[(size_t)B_TOT * R_TOT * C_N];         // b after iter-1 update
__device__ float  g_spart1[(size_t)K1_PARTS * B_TOT * CO];   // k1 partial s
__device__ float  g_spart2[2][(size_t)NCH_R * B_TOT * CO];   // kroute partial s
__device__ int    g_cnt[B_TOT];                              // last-block counters

__device__ __forceinline__ uint32_t smem_u32(const void* p) {
    uint32_t a;
    asm("{ .reg .u64 t; cvta.to.shared.u64 t, %1; cvt.u32.u64 %0, t; }" : "=r"(a) : "l"(p));
    return a;
}

// ---------------------------------------------------------------------------
// K1: u_hat -> fp16 padded tiles, fused softmax(b_init) + s1 partials.
// grid = 16 b-tiles x 64 r-chunks = 1024 blocks, 160 threads (one per (c,o)).
// Round-6 inner loop (72 regs); smaller chunk only raises chip fill.
// ---------------------------------------------------------------------------
__global__ __launch_bounds__(160) void k1(const float* __restrict__ x,
                                          const float* __restrict__ W,
                                          const float* __restrict__ binit) {
    const int bt = blockIdx.x & 15;
    const int rc = blockIdx.x >> 4;          // 0..63 (18-row chunk)
    const int b0 = bt * TB;
    const int tid = threadIdx.x;             // co
    const int c = tid >> 4;
    const int r0 = rc * K1_RC;
    const int chk_g = rc >> 3;               // 144-row tile id (18*8=144)
    const int rin0 = (rc & 7) * K1_RC;       // row offset within tile

    __shared__ float x_sm[TB][K1_RC][I_N];
    __shared__ float c_sm[TB][K1_RC][C_N];

    const float4* W4 = reinterpret_cast<const float4*>(W);
    const float4* x4 = reinterpret_cast<const float4*>(x);

    // stage x tile (float4-coalesced): TB*K1_RC*8 floats
    for (int i = tid; i < TB * K1_RC * 2; i += 160) {
        int bb = i / (K1_RC * 2);
        int rem = i - bb * (K1_RC * 2);
        reinterpret_cast<float4*>(&x_sm[bb][0][0])[rem] =
            x4[((size_t)(b0 + bb) * R_TOT + r0) * 2 + rem];
    }
    // softmax(b_init) for the TB*K1_RC (b,r) pairs
    for (int p = tid; p < TB * K1_RC; p += 160) {
        int bb = p / K1_RC;
        int rr = p - bb * K1_RC;
        const float* bp = binit + ((size_t)(b0 + bb) * R_TOT + r0 + rr) * C_N;
        float e[C_N];
        float m = bp[0];
#pragma unroll
        for (int j = 1; j < C_N; j++) m = fmaxf(m, bp[j]);
        float sum = 0.f;
#pragma unroll
        for (int j = 0; j < C_N; j++) { e[j] = expf(bp[j] - m); sum += e[j]; }
        float inv = 1.f / sum;
#pragma unroll
        for (int j = 0; j < C_N; j++) c_sm[bb][rr][j] = e[j] * inv;
    }
    __syncthreads();

    float s_acc[TB];
#pragma unroll
    for (int i = 0; i < TB; i++) s_acc[i] = 0.f;

    for (int rr = 0; rr < K1_RC; rr++) {
        const int r = r0 + rr;
        const float4* wp = W4 + ((size_t)r * CO + tid) * 2;   // W[r, c, o, :]
        const float4 wa = wp[0];
        const float4 wb = wp[1];
        const int rin = rin0 + rr;
#pragma unroll
        for (int bb = 0; bb < TB; bb++) {
            const float4* xp = reinterpret_cast<const float4*>(&x_sm[bb][rr][0]);
            float4 xa = xp[0], xb = xp[1];
            float uh = wa.x * xa.x + wa.y * xa.y + wa.z * xa.z + wa.w * xa.w
                     + wb.x * xb.x + wb.y * xb.y + wb.z * xb.z + wb.w * xb.w;
            g_uh[((size_t)(b0 + bb) * NCH_R + chk_g) * TILE_H +
                 (size_t)rin * PAD_H + tid] = __float2half_rn(uh);
            s_acc[bb] += c_sm[bb][rr][c] * uh;
        }
    }
#pragma unroll
    for (int bb = 0; bb < TB; bb++)
        g_spart1[((size_t)rc * B_TOT + (b0 + bb)) * CO + tid] = s_acc[bb];
}

// ---------------------------------------------------------------------------
// Fused routing pass (iter = 2 or 3): bulk-copy 48.96KB fp16 tile, overlap
// with in-block v recompute, then agreement -> b update -> softmax -> partial
// s_next. In iter 3, the last block per batch also does the final squash.
// grid = 256 b x 8 chunks = 2048 blocks, 160 threads.
// ---------------------------------------------------------------------------
__global__ __launch_bounds__(160) void kroute(const float* __restrict__ binit,
                                              float* __restrict__ out, int iter) {
    extern __shared__ __align__(16) char smem_raw[];
    __half* uh = reinterpret_cast<__half*>(smem_raw);             // TILE_H halves
    float* cT  = reinterpret_cast<float*>(smem_raw + TILE_BYTES); // [C_N][RCHK]
    float* vs  = cT + C_N * RCHK;                                 // CO
    __shared__ __align__(8) unsigned long long mbar;
    __shared__ int is_last;

    const int b   = blockIdx.x >> 3;
    const int chk = blockIdx.x & 7;
    const int tid = threadIdx.x;

    const uint32_t uh_s = smem_u32(uh);
    const uint32_t mb_s = smem_u32(&mbar);

    if (tid == 0) {
        asm volatile("mbarrier.init.shared.b64 [%0], 1;" :: "r"(mb_s) : "memory");
        asm volatile("mbarrier.arrive.expect_tx.shared.b64 _, [%0], %1;"
                     :: "r"(mb_s), "r"((uint32_t)TILE_BYTES) : "memory");
        const __half* src = g_uh + ((size_t)b * NCH_R + chk) * TILE_H;
        asm volatile("cp.async.bulk.shared::cta.global.mbarrier::complete_tx::bytes "
                     "[%0], [%1], %2, [%3];"
                     :: "r"(uh_s), "l"(src), "r"((uint32_t)TILE_BYTES), "r"(mb_s)
                     : "memory");
    }

    // Overlap with bulk copy: recompute v = squash(sum of prev partials).
    if (tid < CO) {
        float s = 0.f;
        if (iter == 2) {
#pragma unroll 8
            for (int p = 0; p < K1_PARTS; p++)
                s += g_spart1[((size_t)p * B_TOT + b) * CO + tid];
        } else {
#pragma unroll
            for (int p = 0; p < NCH_R; p++)
                s += g_spart2[0][((size_t)p * B_TOT + b) * CO + tid];
        }
        float n = s * s;
#pragma unroll
        for (int off = 8; off >= 1; off >>= 1)
            n += __shfl_xor_sync(0xffffffffu, n, off);
        float scale = (n / (1.f + n)) * rsqrtf(n + 1e-8f);
        vs[tid] = scale * s;
    }
    __syncthreads();

    // wait for bulk copy (phase 0)
    asm volatile(
        "{\n\t.reg .pred P;\n\t"
        "W_%=: mbarrier.try_wait.parity.shared.b64 P, [%0], 0;\n\t"
        "@!P bra W_%=;\n\t}"
        :: "r"(mb_s) : "memory");

    // Phase A: agreement + b update + softmax. 1 thread per row.
    if (tid < RCHK) {
        const int r = chk * RCHK + tid;
        const float* bin = (iter == 2) ? (binit + ((size_t)b * R_TOT + r) * C_N)
                                       : (g_b2  + ((size_t)b * R_TOT + r) * C_N);
        const __half2* urow = reinterpret_cast<const __half2*>(uh + tid * PAD_H);
        float bv[C_N];
#pragma unroll
        for (int cc = 0; cc < C_N; cc++) {
            float a = 0.f;
#pragma unroll
            for (int k = 0; k < 8; k++) {
                float2 f = __half22float2(urow[cc * 8 + k]);
                a = fmaf(f.x, vs[cc * 16 + 2 * k], a);
                a = fmaf(f.y, vs[cc * 16 + 2 * k + 1], a);
            }
            bv[cc] = bin[cc] + a;
        }
        if (iter == 2) {
            float* bo = g_b2 + ((size_t)b * R_TOT + r) * C_N;
#pragma unroll
            for (int cc = 0; cc < C_N; cc++) bo[cc] = bv[cc];
        }
        float m = bv[0];
#pragma unroll
        for (int cc = 1; cc < C_N; cc++) m = fmaxf(m, bv[cc]);
        float e[C_N], sum = 0.f;
#pragma unroll
        for (int cc = 0; cc < C_N; cc++) { e[cc] = expf(bv[cc] - m); sum += e[cc]; }
        float inv = 1.f / sum;
#pragma unroll
        for (int cc = 0; cc < C_N; cc++) cT[cc * RCHK + tid] = e[cc] * inv;
    }
    __syncthreads();

    // Phase B: s partial; thread = (c,o), loop rows.
    {
        const int cc = tid >> 4;
        const float* crow = cT + cc * RCHK;
        float acc = 0.f;
#pragma unroll 4
        for (int r = 0; r < RCHK; r++)
            acc = fmaf(crow[r], __half2float(uh[r * PAD_H + tid]), acc);
        const int slot = (iter == 2) ? 0 : 1;
        g_spart2[slot][((size_t)chk * B_TOT + b) * CO + tid] = acc;
    }

    // Iter 3: last block per batch performs the final squash -> out.
    if (iter == 3) {
        __threadfence();
        __syncthreads();
        if (tid == 0) {
            int prev = atomicAdd(&g_cnt[b], 1);
            is_last = (prev == NCH_R - 1);
        }
        __syncthreads();
        if (is_last) {
            __threadfence();
            if (tid < CO) {
                float s = 0.f;
#pragma unroll
                for (int p = 0; p < NCH_R; p++)
                    s += g_spart2[1][((size_t)p * B_TOT + b) * CO + tid];
                float n = s * s;
#pragma unroll
                for (int off = 8; off >= 1; off >>= 1)
                    n += __shfl_xor_sync(0xffffffffu, n, off);
                float scale = (n / (1.f + n)) * rsqrtf(n + 1e-8f);
                out[(size_t)b * CO + tid] = scale * s;
            }
            if (tid == 0) g_cnt[b] = 0;   // reset for next graph replay
        }
    }
}

// ---------------------------------------------------------------------------
extern "C" void kernel_launch(void* const* d_in, const int* in_sizes, int n_in,
                              void* d_out, int out_size) {
    const float *x = nullptr, *W = nullptr, *binit = nullptr;
    for (int i = 0; i < n_in; i++) {
        if (in_sizes[i] == B_TOT * R_TOT * I_N)          x     = (const float*)d_in[i];
        else if (in_sizes[i] == R_TOT * C_N * O_N * I_N) W     = (const float*)d_in[i];
        else if (in_sizes[i] == B_TOT * R_TOT * C_N)     binit = (const float*)d_in[i];
    }
    float* out = (float*)d_out;

    const int SMEM_ROUTE = TILE_BYTES + (C_N * RCHK + CO) * (int)sizeof(float);
    cudaFuncSetAttribute(kroute, cudaFuncAttributeMaxDynamicSharedMemorySize, SMEM_ROUTE);

    // iter 1: u_hat (fp16) + s1 partials
    k1<<<1024, 160>>>(x, W, binit);
    // iter 2: v1 (in-block) + agreement + b2 + softmax + s2
    kroute<<<2048, 160, SMEM_ROUTE>>>(binit, out, 2);
    // iter 3: v2 (in-block) + agreement + softmax + s3 + fused final squash
    kroute<<<2048, 160, SMEM_ROUTE>>>(binit, out, 3);
}

// round 9
// speedup vs baseline: 1.3601x; 1.2730x over previous
#include <cuda_runtime.h>
#include <cuda_fp16.h>
#include <cstdint>

#define R_TOT 1152
#define B_TOT 256
#define C_N 10
#define O_N 16
#define CO 160
#define I_N 8

// kroute tiling
#define NCH_R 8            // route chunks per batch
#define RCHK 144           // rows per route chunk
#define PAD_H 170          // fp16 row stride (340B, odd halves -> conflict-free)
#define TILE_H (RCHK * PAD_H)          // 24480 halves
#define TILE_BYTES (TILE_H * 2)        // 48960 (16B multiple)

// k1 tiling
#define TB 16              // batches per k1 block
#define K1_RC 36           // rows per k1 block
#define K1_NCH 32          // 1152/36 r-chunks
#define K1_PARTS 32        // s1 partial chunks

// Scratch (device globals: allocation-free kernel_launch)
__device__ __half g_uh[(size_t)B_TOT * NCH_R * TILE_H];      // ~100 MB fp16 (fits L2)
__device__ __half2 g_wh[(size_t)R_TOT * 80 * I_N];           // W packed: [r][u][i] = (W[r,2u,i],W[r,2u+1,i])
__device__ float  g_b2[(size_t)B_TOT * R_TOT * C_N];         // b after iter-1 update
__device__ float  g_spart1[(size_t)K1_PARTS * B_TOT * CO];   // k1 partial s
__device__ float  g_spart2[2][(size_t)NCH_R * B_TOT * CO];   // kroute partial s
__device__ int    g_cnt[B_TOT];                              // last-block counters

__device__ __forceinline__ uint32_t smem_u32(const void* p) {
    uint32_t a;
    asm("{ .reg .u64 t; cvta.to.shared.u64 t, %1; cvt.u32.u64 %0, t; }" : "=r"(a) : "l"(p));
    return a;
}

// ---------------------------------------------------------------------------
// K0: pack W (fp32 [R, CO, I]) into column-pair half2 layout [r][u][i].
// ---------------------------------------------------------------------------
__global__ __launch_bounds__(256) void k0(const float* __restrict__ W) {
    int idx = blockIdx.x * 256 + threadIdx.x;        // over R_TOT*80*8
    if (idx >= R_TOT * 80 * I_N) return;
    int i = idx & 7;
    int t = idx >> 3;
    int u = t % 80;
    int r = t / 80;
    float w0 = W[((size_t)r * CO + 2 * u) * I_N + i];
    float w1 = W[((size_t)r * CO + 2 * u + 1) * I_N + i];
    g_wh[idx] = __floats2half2_rn(w0, w1);
}

// ---------------------------------------------------------------------------
// K1: u_hat via HFMA2 (fp16 math, 2 columns/thread) -> fp16 padded tiles,
// fused softmax(b_init) + fp32 s1 partials.
// grid = 16 b-tiles x 32 r-chunks = 512 blocks, 160 threads:
//   grp = tid/80 picks 8 of the 16 batches; u = tid%80 picks column pair.
// ---------------------------------------------------------------------------
__global__ __launch_bounds__(160) void k1(const float* __restrict__ x,
                                          const float* __restrict__ binit) {
    const int bt = blockIdx.x & 15;
    const int rc = blockIdx.x >> 4;          // 0..31 (36-row chunk)
    const int b0 = bt * TB;
    const int tid = threadIdx.x;
    const int r0 = rc * K1_RC;
    const int chk_g = rc >> 2;               // 144-row tile id
    const int rin0 = (rc & 3) * K1_RC;       // row offset within tile

    const int grp = tid / 80;                // batch half
    const int u   = tid - grp * 80;          // column pair (cols 2u, 2u+1)
    const int c   = u >> 3;                  // capsule (same for both cols)
    const int bb0 = grp * 8;

    __shared__ __half2 x2_sm[TB][K1_RC][I_N];   // duplicated-lane x, 18.4KB
    __shared__ float   c_sm[TB][K1_RC][C_N];    // routing coeffs, 23KB

    const float4* x4 = reinterpret_cast<const float4*>(x);

    // stage x as duplicated half2 (one float4 -> four half2, STS.128)
    for (int i = tid; i < TB * K1_RC * 2; i += 160) {
        int bb = i / (K1_RC * 2);
        int rem = i - bb * (K1_RC * 2);
        float4 v = x4[((size_t)(b0 + bb) * R_TOT + r0) * 2 + rem];
        __half2* dst = &x2_sm[bb][0][0] + rem * 4;
        dst[0] = __float2half2_rn(v.x);
        dst[1] = __float2half2_rn(v.y);
        dst[2] = __float2half2_rn(v.z);
        dst[3] = __float2half2_rn(v.w);
    }
    // softmax(b_init)
    for (int p = tid; p < TB * K1_RC; p += 160) {
        int bb = p / K1_RC;
        int rr = p - bb * K1_RC;
        const float* bp = binit + ((size_t)(b0 + bb) * R_TOT + r0 + rr) * C_N;
        float e[C_N];
        float m = bp[0];
#pragma unroll
        for (int j = 1; j < C_N; j++) m = fmaxf(m, bp[j]);
        float sum = 0.f;
#pragma unroll
        for (int j = 0; j < C_N; j++) { e[j] = expf(bp[j] - m); sum += e[j]; }
        float inv = 1.f / sum;
#pragma unroll
        for (int j = 0; j < C_N; j++) c_sm[bb][rr][j] = e[j] * inv;
    }
    __syncthreads();

    float2 s_acc[8];
#pragma unroll
    for (int i = 0; i < 8; i++) s_acc[i] = make_float2(0.f, 0.f);

    for (int rr = 0; rr < K1_RC; rr++) {
        const int r = r0 + rr;
        const int rin = rin0 + rr;
        // W column pair: 8 half2 = 2x LDG.128, coalesced across u
        __half2 w[8];
        {
            const uint4* wp = reinterpret_cast<const uint4*>(g_wh + ((size_t)r * 80 + u) * I_N);
            uint4 a = wp[0], bq = wp[1];
            w[0] = *reinterpret_cast<__half2*>(&a.x);
            w[1] = *reinterpret_cast<__half2*>(&a.y);
            w[2] = *reinterpret_cast<__half2*>(&a.z);
            w[3] = *reinterpret_cast<__half2*>(&a.w);
            w[4] = *reinterpret_cast<__half2*>(&bq.x);
            w[5] = *reinterpret_cast<__half2*>(&bq.y);
            w[6] = *reinterpret_cast<__half2*>(&bq.z);
            w[7] = *reinterpret_cast<__half2*>(&bq.w);
        }
#pragma unroll
        for (int bbl = 0; bbl < 8; bbl++) {
            const int bb = bb0 + bbl;
            const __half2* xh = &x2_sm[bb][rr][0];
            __half2 acc = __hmul2(w[0], xh[0]);
            acc = __hfma2(w[1], xh[1], acc);
            acc = __hfma2(w[2], xh[2], acc);
            acc = __hfma2(w[3], xh[3], acc);
            acc = __hfma2(w[4], xh[4], acc);
            acc = __hfma2(w[5], xh[5], acc);
            acc = __hfma2(w[6], xh[6], acc);
            acc = __hfma2(w[7], xh[7], acc);
            // one STG.32 stores both columns
            __half2* dst = reinterpret_cast<__half2*>(
                g_uh + ((size_t)(b0 + bb) * NCH_R + chk_g) * TILE_H + (size_t)rin * PAD_H);
            dst[u] = acc;
            float2 f = __half22float2(acc);
            const float cf = c_sm[bb][rr][c];
            s_acc[bbl].x = fmaf(cf, f.x, s_acc[bbl].x);
            s_acc[bbl].y = fmaf(cf, f.y, s_acc[bbl].y);
        }
    }
#pragma unroll
    for (int bbl = 0; bbl < 8; bbl++) {
        float2* sp = reinterpret_cast<float2*>(
            g_spart1 + ((size_t)rc * B_TOT + (b0 + bb0 + bbl)) * CO);
        sp[u] = s_acc[bbl];
    }
}

// ---------------------------------------------------------------------------
// Fused routing pass (iter = 2 or 3): bulk-copy 48.96KB fp16 tile, overlap
// with in-block v recompute, then agreement -> b update -> softmax -> partial
// s_next. In iter 3, the last block per batch also does the final squash.
// grid = 256 b x 8 chunks = 2048 blocks, 160 threads.
// ---------------------------------------------------------------------------
__global__ __launch_bounds__(160) void kroute(const float* __restrict__ binit,
                                              float* __restrict__ out, int iter) {
    extern __shared__ __align__(16) char smem_raw[];
    __half* uh = reinterpret_cast<__half*>(smem_raw);             // TILE_H halves
    float* cT  = reinterpret_cast<float*>(smem_raw + TILE_BYTES); // [C_N][RCHK]
    float* vs  = cT + C_N * RCHK;                                 // CO
    __shared__ __align__(8) unsigned long long mbar;
    __shared__ int is_last;

    const int b   = blockIdx.x >> 3;
    const int chk = blockIdx.x & 7;
    const int tid = threadIdx.x;

    const uint32_t uh_s = smem_u32(uh);
    const uint32_t mb_s = smem_u32(&mbar);

    if (tid == 0) {
        asm volatile("mbarrier.init.shared.b64 [%0], 1;" :: "r"(mb_s) : "memory");
        asm volatile("mbarrier.arrive.expect_tx.shared.b64 _, [%0], %1;"
                     :: "r"(mb_s), "r"((uint32_t)TILE_BYTES) : "memory");
        const __half* src = g_uh + ((size_t)b * NCH_R + chk) * TILE_H;
        asm volatile("cp.async.bulk.shared::cta.global.mbarrier::complete_tx::bytes "
                     "[%0], [%1], %2, [%3];"
                     :: "r"(uh_s), "l"(src), "r"((uint32_t)TILE_BYTES), "r"(mb_s)
                     : "memory");
    }

    // Overlap with bulk copy: recompute v = squash(sum of prev partials).
    if (tid < CO) {
        float s = 0.f;
        if (iter == 2) {
#pragma unroll
            for (int p = 0; p < K1_PARTS; p++)
                s += g_spart1[((size_t)p * B_TOT + b) * CO + tid];
        } else {
#pragma unroll
            for (int p = 0; p < NCH_R; p++)
                s += g_spart2[0][((size_t)p * B_TOT + b) * CO + tid];
        }
        float n = s * s;
#pragma unroll
        for (int off = 8; off >= 1; off >>= 1)
            n += __shfl_xor_sync(0xffffffffu, n, off);
        float scale = (n / (1.f + n)) * rsqrtf(n + 1e-8f);
        vs[tid] = scale * s;
    }
    __syncthreads();

    // wait for bulk copy (phase 0)
    asm volatile(
        "{\n\t.reg .pred P;\n\t"
        "W_%=: mbarrier.try_wait.parity.shared.b64 P, [%0], 0;\n\t"
        "@!P bra W_%=;\n\t}"
        :: "r"(mb_s) : "memory");

    // Phase A: agreement + b update + softmax. 1 thread per row.
    if (tid < RCHK) {
        const int r = chk * RCHK + tid;
        const float* bin = (iter == 2) ? (binit + ((size_t)b * R_TOT + r) * C_N)
                                       : (g_b2  + ((size_t)b * R_TOT + r) * C_N);
        const __half2* urow = reinterpret_cast<const __half2*>(uh + tid * PAD_H);
        float bv[C_N];
#pragma unroll
        for (int cc = 0; cc < C_N; cc++) {
            float a = 0.f;
#pragma unroll
            for (int k = 0; k < 8; k++) {
                float2 f = __half22float2(urow[cc * 8 + k]);
                a = fmaf(f.x, vs[cc * 16 + 2 * k], a);
                a = fmaf(f.y, vs[cc * 16 + 2 * k + 1], a);
            }
            bv[cc] = bin[cc] + a;
        }
        if (iter == 2) {
            float* bo = g_b2 + ((size_t)b * R_TOT + r) * C_N;
#pragma unroll
            for (int cc = 0; cc < C_N; cc++) bo[cc] = bv[cc];
        }
        float m = bv[0];
#pragma unroll
        for (int cc = 1; cc < C_N; cc++) m = fmaxf(m, bv[cc]);
        float e[C_N], sum = 0.f;
#pragma unroll
        for (int cc = 0; cc < C_N; cc++) { e[cc] = expf(bv[cc] - m); sum += e[cc]; }
        float inv = 1.f / sum;
#pragma unroll
        for (int cc = 0; cc < C_N; cc++) cT[cc * RCHK + tid] = e[cc] * inv;
    }
    __syncthreads();

    // Phase B: s partial; thread = (c,o), loop rows.
    {
        const int cc = tid >> 4;
        const float* crow = cT + cc * RCHK;
        float acc = 0.f;
#pragma unroll 4
        for (int r = 0; r < RCHK; r++)
            acc = fmaf(crow[r], __half2float(uh[r * PAD_H + tid]), acc);
        const int slot = (iter == 2) ? 0 : 1;
        g_spart2[slot][((size_t)chk * B_TOT + b) * CO + tid] = acc;
    }

    // Iter 3: last block per batch performs the final squash -> out.
    if (iter == 3) {
        __threadfence();
        __syncthreads();
        if (tid == 0) {
            int prev = atomicAdd(&g_cnt[b], 1);
            is_last = (prev == NCH_R - 1);
        }
        __syncthreads();
        if (is_last) {
            __threadfence();
            if (tid < CO) {
                float s = 0.f;
#pragma unroll
                for (int p = 0; p < NCH_R; p++)
                    s += g_spart2[1][((size_t)p * B_TOT + b) * CO + tid];
                float n = s * s;
#pragma unroll
                for (int off = 8; off >= 1; off >>= 1)
                    n += __shfl_xor_sync(0xffffffffu, n, off);
                float scale = (n / (1.f + n)) * rsqrtf(n + 1e-8f);
                out[(size_t)b * CO + tid] = scale * s;
            }
            if (tid == 0) g_cnt[b] = 0;   // reset for next graph replay
        }
    }
}

// ---------------------------------------------------------------------------
extern "C" void kernel_launch(void* const* d_in, const int* in_sizes, int n_in,
                              void* d_out, int out_size) {
    const float *x = nullptr, *W = nullptr, *binit = nullptr;
    for (int i = 0; i < n_in; i++) {
        if (in_sizes[i] == B_TOT * R_TOT * I_N)          x     = (const float*)d_in[i];
        else if (in_sizes[i] == R_TOT * C_N * O_N * I_N) W     = (const float*)d_in[i];
        else if (in_sizes[i] == B_TOT * R_TOT * C_N)     binit = (const float*)d_in[i];
    }
    float* out = (float*)d_out;

    const int SMEM_ROUTE = TILE_BYTES + (C_N * RCHK + CO) * (int)sizeof(float);
    cudaFuncSetAttribute(kroute, cudaFuncAttributeMaxDynamicSharedMemorySize, SMEM_ROUTE);

    // pack W into fp16 column pairs
    k0<<<(R_TOT * 80 * I_N + 255) / 256, 256>>>(W);
    // iter 1: u_hat (fp16 HFMA2) + s1 partials
    k1<<<512, 160>>>(x, binit);
    // iter 2: v1 (in-block) + agreement + b2 + softmax + s2
    kroute<<<2048, 160, SMEM_ROUTE>>>(binit, out, 2);
    // iter 3: v2 (in-block) + agreement + softmax + s3 + fused final squash
    kroute<<<2048, 160, SMEM_ROUTE>>>(binit, out, 3);
}

// round 10
// speedup vs baseline: 1.3638x; 1.0027x over previous
#include <cuda_runtime.h>
#include <cuda_fp16.h>
#include <cstdint>

#define R_TOT 1152
#define B_TOT 256
#define C_N 10
#define O_N 16
#define CO 160
#define I_N 8

// kroute tiling
#define NCH_R 16           // route chunks per batch
#define RCHK 72            // rows per route chunk
#define PAD_H 170          // fp16 row stride (340B, odd halves -> conflict-free)
#define TILE_H (RCHK * PAD_H)          // 12240 halves
#define TILE_BYTES (TILE_H * 2)        // 24480 (16B multiple)

// k1 tiling
#define TB 16              // batches per k1 block
#define K1_RC 36           // rows per k1 block
#define K1_NCH 32          // 1152/36 r-chunks
#define K1_PARTS 32        // s1 partial chunks

// Scratch (device globals: allocation-free kernel_launch)
__device__ __half g_uh[(size_t)B_TOT * NCH_R * TILE_H];      // ~100 MB fp16
__device__ __half2 g_wh[(size_t)R_TOT * 80 * I_N];           // W packed column pairs
__device__ float  g_b2[(size_t)B_TOT * R_TOT * C_N];         // b after iter-1 update
__device__ float  g_spart1[(size_t)K1_PARTS * B_TOT * CO];   // k1 partial s
__device__ float  g_spart2[2][(size_t)NCH_R * B_TOT * CO];   // kroute partial s
__device__ int    g_cnt[B_TOT];                              // last-block counters

__device__ __forceinline__ uint32_t smem_u32(const void* p) {
    uint32_t a;
    asm("{ .reg .u64 t; cvta.to.shared.u64 t, %1; cvt.u32.u64 %0, t; }" : "=r"(a) : "l"(p));
    return a;
}

// ---------------------------------------------------------------------------
// K0: pack W (fp32 [R, CO, I]) into column-pair half2 layout [r][u][i].
// ---------------------------------------------------------------------------
__global__ __launch_bounds__(256) void k0(const float* __restrict__ W) {
    int idx = blockIdx.x * 256 + threadIdx.x;        // over R_TOT*80*8
    if (idx >= R_TOT * 80 * I_N) return;
    int i = idx & 7;
    int t = idx >> 3;
    int u = t % 80;
    int r = t / 80;
    float w0 = W[((size_t)r * CO + 2 * u) * I_N + i];
    float w1 = W[((size_t)r * CO + 2 * u + 1) * I_N + i];
    g_wh[idx] = __floats2half2_rn(w0, w1);
}

// ---------------------------------------------------------------------------
// K1: u_hat via HFMA2 (2 columns/thread) -> fp16 padded tiles, fused
// softmax(b_init) + fp32 s1 partials. x loads vectorized to LDS.128.
// grid = 16 b-tiles x 32 r-chunks = 512 blocks, 160 threads.
// ---------------------------------------------------------------------------
__global__ __launch_bounds__(160) void k1(const float* __restrict__ x,
                                          const float* __restrict__ binit) {
    const int bt = blockIdx.x & 15;
    const int rc = blockIdx.x >> 4;          // 0..31 (36-row chunk)
    const int b0 = bt * TB;
    const int tid = threadIdx.x;
    const int r0 = rc * K1_RC;
    const int chk_g = rc >> 1;               // 72-row tile id
    const int rin0 = (rc & 1) * K1_RC;       // row offset within tile

    const int grp = tid / 80;                // batch half
    const int u   = tid - grp * 80;          // column pair (cols 2u, 2u+1)
    const int c   = u >> 3;                  // capsule (same for both cols)
    const int bb0 = grp * 8;

    __shared__ __half2 x2_sm[TB][K1_RC][I_N];   // duplicated-lane x (32B rows)
    __shared__ float   c_sm[TB][K1_RC][C_N];    // routing coeffs

    const float4* x4 = reinterpret_cast<const float4*>(x);

    // stage x as duplicated half2 (one float4 -> four half2)
    for (int i = tid; i < TB * K1_RC * 2; i += 160) {
        int bb = i / (K1_RC * 2);
        int rem = i - bb * (K1_RC * 2);
        float4 v = x4[((size_t)(b0 + bb) * R_TOT + r0) * 2 + rem];
        __half2* dst = &x2_sm[bb][0][0] + rem * 4;
        dst[0] = __float2half2_rn(v.x);
        dst[1] = __float2half2_rn(v.y);
        dst[2] = __float2half2_rn(v.z);
        dst[3] = __float2half2_rn(v.w);
    }
    // softmax(b_init)
    for (int p = tid; p < TB * K1_RC; p += 160) {
        int bb = p / K1_RC;
        int rr = p - bb * K1_RC;
        const float* bp = binit + ((size_t)(b0 + bb) * R_TOT + r0 + rr) * C_N;
        float e[C_N];
        float m = bp[0];
#pragma unroll
        for (int j = 1; j < C_N; j++) m = fmaxf(m, bp[j]);
        float sum = 0.f;
#pragma unroll
        for (int j = 0; j < C_N; j++) { e[j] = expf(bp[j] - m); sum += e[j]; }
        float inv = 1.f / sum;
#pragma unroll
        for (int j = 0; j < C_N; j++) c_sm[bb][rr][j] = e[j] * inv;
    }
    __syncthreads();

    float2 s_acc[8];
#pragma unroll
    for (int i = 0; i < 8; i++) s_acc[i] = make_float2(0.f, 0.f);

    for (int rr = 0; rr < K1_RC; rr++) {
        const int r = r0 + rr;
        const int rin = rin0 + rr;
        // W column pair: 2x LDG.128, coalesced across u
        __half2 w[8];
        {
            const uint4* wp = reinterpret_cast<const uint4*>(g_wh + ((size_t)r * 80 + u) * I_N);
            uint4 a = wp[0], bq = wp[1];
            w[0] = *reinterpret_cast<__half2*>(&a.x);
            w[1] = *reinterpret_cast<__half2*>(&a.y);
            w[2] = *reinterpret_cast<__half2*>(&a.z);
            w[3] = *reinterpret_cast<__half2*>(&a.w);
            w[4] = *reinterpret_cast<__half2*>(&bq.x);
            w[5] = *reinterpret_cast<__half2*>(&bq.y);
            w[6] = *reinterpret_cast<__half2*>(&bq.z);
            w[7] = *reinterpret_cast<__half2*>(&bq.w);
        }
#pragma unroll
        for (int bbl = 0; bbl < 8; bbl++) {
            const int bb = bb0 + bbl;
            // x row: 2x LDS.128 (8 half2 = 32B contiguous)
            const uint4* xq = reinterpret_cast<const uint4*>(&x2_sm[bb][rr][0]);
            uint4 xa = xq[0], xb = xq[1];
            __half2 x0 = *reinterpret_cast<__half2*>(&xa.x);
            __half2 x1 = *reinterpret_cast<__half2*>(&xa.y);
            __half2 x2 = *reinterpret_cast<__half2*>(&xa.z);
            __half2 x3 = *reinterpret_cast<__half2*>(&xa.w);
            __half2 x4h = *reinterpret_cast<__half2*>(&xb.x);
            __half2 x5 = *reinterpret_cast<__half2*>(&xb.y);
            __half2 x6 = *reinterpret_cast<__half2*>(&xb.z);
            __half2 x7 = *reinterpret_cast<__half2*>(&xb.w);
            __half2 acc = __hmul2(w[0], x0);
            acc = __hfma2(w[1], x1, acc);
            acc = __hfma2(w[2], x2, acc);
            acc = __hfma2(w[3], x3, acc);
            acc = __hfma2(w[4], x4h, acc);
            acc = __hfma2(w[5], x5, acc);
            acc = __hfma2(w[6], x6, acc);
            acc = __hfma2(w[7], x7, acc);
            __half2* dst = reinterpret_cast<__half2*>(
                g_uh + ((size_t)(b0 + bb) * NCH_R + chk_g) * TILE_H + (size_t)rin * PAD_H);
            dst[u] = acc;
            float2 f = __half22float2(acc);
            const float cf = c_sm[bb][rr][c];
            s_acc[bbl].x = fmaf(cf, f.x, s_acc[bbl].x);
            s_acc[bbl].y = fmaf(cf, f.y, s_acc[bbl].y);
        }
    }
#pragma unroll
    for (int bbl = 0; bbl < 8; bbl++) {
        float2* sp = reinterpret_cast<float2*>(
            g_spart1 + ((size_t)rc * B_TOT + (b0 + bb0 + bbl)) * CO);
        sp[u] = s_acc[bbl];
    }
}

// ---------------------------------------------------------------------------
// Fused routing pass (iter = 2 or 3): bulk-copy 24.48KB fp16 tile (8 blk/SM
// -> deep TMA pipeline), overlap with v recompute, then agreement -> b update
// -> softmax -> partial s. Iter 3 last block per batch does final squash.
// grid = 256 b x 16 chunks = 4096 blocks, 160 threads, 28KB SMEM.
// ---------------------------------------------------------------------------
__global__ __launch_bounds__(160) void kroute(const float* __restrict__ binit,
                                              float* __restrict__ out, int iter) {
    extern __shared__ __align__(16) char smem_raw[];
    __half* uh = reinterpret_cast<__half*>(smem_raw);             // TILE_H halves
    float* cT  = reinterpret_cast<float*>(smem_raw + TILE_BYTES); // [C_N][RCHK]
    float* vs  = cT + C_N * RCHK;                                 // CO
    __shared__ __align__(8) unsigned long long mbar;
    __shared__ int is_last;

    const int b   = blockIdx.x >> 4;
    const int chk = blockIdx.x & 15;
    const int tid = threadIdx.x;

    const uint32_t uh_s = smem_u32(uh);
    const uint32_t mb_s = smem_u32(&mbar);

    if (tid == 0) {
        asm volatile("mbarrier.init.shared.b64 [%0], 1;" :: "r"(mb_s) : "memory");
        asm volatile("mbarrier.arrive.expect_tx.shared.b64 _, [%0], %1;"
                     :: "r"(mb_s), "r"((uint32_t)TILE_BYTES) : "memory");
        const __half* src = g_uh + ((size_t)b * NCH_R + chk) * TILE_H;
        asm volatile("cp.async.bulk.shared::cta.global.mbarrier::complete_tx::bytes "
                     "[%0], [%1], %2, [%3];"
                     :: "r"(uh_s), "l"(src), "r"((uint32_t)TILE_BYTES), "r"(mb_s)
                     : "memory");
    }

    // Overlap with bulk copy: recompute v = squash(sum of prev partials).
    if (tid < CO) {
        float s = 0.f;
        if (iter == 2) {
#pragma unroll
            for (int p = 0; p < K1_PARTS; p++)
                s += g_spart1[((size_t)p * B_TOT + b) * CO + tid];
        } else {
#pragma unroll
            for (int p = 0; p < NCH_R; p++)
                s += g_spart2[0][((size_t)p * B_TOT + b) * CO + tid];
        }
        float n = s * s;
#pragma unroll
        for (int off = 8; off >= 1; off >>= 1)
            n += __shfl_xor_sync(0xffffffffu, n, off);
        float scale = (n / (1.f + n)) * rsqrtf(n + 1e-8f);
        vs[tid] = scale * s;
    }
    __syncthreads();

    // wait for bulk copy (phase 0)
    asm volatile(
        "{\n\t.reg .pred P;\n\t"
        "W_%=: mbarrier.try_wait.parity.shared.b64 P, [%0], 0;\n\t"
        "@!P bra W_%=;\n\t}"
        :: "r"(mb_s) : "memory");

    // Phase A: agreement + b update + softmax. 2 threads/row, 5 caps each.
    const unsigned mask = __ballot_sync(0xffffffffu, tid < 2 * RCHK);
    if (tid < 2 * RCHK) {
        const int row = tid >> 1;
        const int c0  = (tid & 1) * 5;
        const int r   = chk * RCHK + row;
        const float* bin = (iter == 2) ? (binit + ((size_t)b * R_TOT + r) * C_N)
                                       : (g_b2  + ((size_t)b * R_TOT + r) * C_N);
        const __half2* urow = reinterpret_cast<const __half2*>(uh + row * PAD_H);
        float bv[5];
#pragma unroll
        for (int j = 0; j < 5; j++) {
            const int cc = c0 + j;
            float a = 0.f;
#pragma unroll
            for (int k = 0; k < 8; k++) {
                float2 f = __half22float2(urow[cc * 8 + k]);
                a = fmaf(f.x, vs[cc * 16 + 2 * k], a);
                a = fmaf(f.y, vs[cc * 16 + 2 * k + 1], a);
            }
            bv[j] = bin[cc] + a;
        }
        if (iter == 2) {  // persist b2 for iteration 3
            float* bo = g_b2 + ((size_t)b * R_TOT + r) * C_N;
#pragma unroll
            for (int j = 0; j < 5; j++) bo[c0 + j] = bv[j];
        }
        float m = bv[0];
#pragma unroll
        for (int j = 1; j < 5; j++) m = fmaxf(m, bv[j]);
        m = fmaxf(m, __shfl_xor_sync(mask, m, 1));
        float e[5], ps = 0.f;
#pragma unroll
        for (int j = 0; j < 5; j++) { e[j] = expf(bv[j] - m); ps += e[j]; }
        ps += __shfl_xor_sync(mask, ps, 1);
        const float inv = 1.f / ps;
#pragma unroll
        for (int j = 0; j < 5; j++) cT[(c0 + j) * RCHK + row] = e[j] * inv;
    }
    __syncthreads();

    // Phase B: s partial; thread = (c,o), loop rows.
    {
        const int cc = tid >> 4;
        const float* crow = cT + cc * RCHK;
        float acc = 0.f;
#pragma unroll 4
        for (int r = 0; r < RCHK; r++)
            acc = fmaf(crow[r], __half2float(uh[r * PAD_H + tid]), acc);
        const int slot = (iter == 2) ? 0 : 1;
        g_spart2[slot][((size_t)chk * B_TOT + b) * CO + tid] = acc;
    }

    // Iter 3: last block per batch performs the final squash -> out.
    if (iter == 3) {
        __threadfence();
        __syncthreads();
        if (tid == 0) {
            int prev = atomicAdd(&g_cnt[b], 1);
            is_last = (prev == NCH_R - 1);
        }
        __syncthreads();
        if (is_last) {
            __threadfence();
            if (tid < CO) {
                float s = 0.f;
#pragma unroll
                for (int p = 0; p < NCH_R; p++)
                    s += g_spart2[1][((size_t)p * B_TOT + b) * CO + tid];
                float n = s * s;
#pragma unroll
                for (int off = 8; off >= 1; off >>= 1)
                    n += __shfl_xor_sync(0xffffffffu, n, off);
                float scale = (n / (1.f + n)) * rsqrtf(n + 1e-8f);
                out[(size_t)b * CO + tid] = scale * s;
            }
            if (tid == 0) g_cnt[b] = 0;   // reset for next graph replay
        }
    }
}

// ---------------------------------------------------------------------------
extern "C" void kernel_launch(void* const* d_in, const int* in_sizes, int n_in,
                              void* d_out, int out_size) {
    const float *x = nullptr, *W = nullptr, *binit = nullptr;
    for (int i = 0; i < n_in; i++) {
        if (in_sizes[i] == B_TOT * R_TOT * I_N)          x     = (const float*)d_in[i];
        else if (in_sizes[i] == R_TOT * C_N * O_N * I_N) W     = (const float*)d_in[i];
        else if (in_sizes[i] == B_TOT * R_TOT * C_N)     binit = (const float*)d_in[i];
    }
    float* out = (float*)d_out;

    const int SMEM_ROUTE = TILE_BYTES + (C_N * RCHK + CO) * (int)sizeof(float);
    cudaFuncSetAttribute(kroute, cudaFuncAttributeMaxDynamicSharedMemorySize, SMEM_ROUTE);

    // pack W into fp16 column pairs
    k0<<<(R_TOT * 80 * I_N + 255) / 256, 256>>>(W);
    // iter 1: u_hat (fp16 HFMA2) + s1 partials
    k1<<<512, 160>>>(x, binit);
    // iter 2: v1 (in-block) + agreement + b2 + softmax + s2
    kroute<<<4096, 160, SMEM_ROUTE>>>(binit, out, 2);
    // iter 3: v2 (in-block) + agreement + softmax + s3 + fused final squash
    kroute<<<4096, 160, SMEM_ROUTE>>>(binit, out, 3);
}

// round 11
// speedup vs baseline: 1.3866x; 1.0167x over previous
#include <cuda_runtime.h>
#include <cuda_fp16.h>
#include <cstdint>

#define R_TOT 1152
#define B_TOT 256
#define C_N 10
#define O_N 16
#define CO 160
#define I_N 8

// kroute tiling
#define NCH_R 16           // route chunks per batch
#define RCHK 72            // rows per route chunk
#define PAD_H 168          // fp16 row stride: 336B rows, 16B-aligned for LDS.128
#define TILE_H (RCHK * PAD_H)          // 12096 halves
#define TILE_BYTES (TILE_H * 2)        // 24192 (16B multiple)

// k1 tiling
#define TB 16              // batches per k1 block
#define K1_RC 36           // rows per k1 block
#define K1_NCH 32          // 1152/36 r-chunks
#define K1_PARTS 32        // s1 partial chunks

// Scratch (device globals: allocation-free kernel_launch)
__device__ __half g_uh[(size_t)B_TOT * NCH_R * TILE_H];      // ~99 MB fp16
__device__ __half2 g_wh[(size_t)R_TOT * 80 * I_N];           // W packed column pairs
__device__ float  g_b2[(size_t)B_TOT * R_TOT * C_N];         // b after iter-1 update
__device__ float  g_spart1[(size_t)K1_PARTS * B_TOT * CO];   // k1 partial s
__device__ float  g_spart2[2][(size_t)NCH_R * B_TOT * CO];   // kroute partial s
__device__ int    g_cnt[B_TOT];                              // last-block counters

__device__ __forceinline__ uint32_t smem_u32(const void* p) {
    uint32_t a;
    asm("{ .reg .u64 t; cvta.to.shared.u64 t, %1; cvt.u32.u64 %0, t; }" : "=r"(a) : "l"(p));
    return a;
}

// ---------------------------------------------------------------------------
// K0: pack W (fp32 [R, CO, I]) into column-pair half2 layout [r][u][i].
// ---------------------------------------------------------------------------
__global__ __launch_bounds__(256) void k0(const float* __restrict__ W) {
    int idx = blockIdx.x * 256 + threadIdx.x;        // over R_TOT*80*8
    if (idx >= R_TOT * 80 * I_N) return;
    int i = idx & 7;
    int t = idx >> 3;
    int u = t % 80;
    int r = t / 80;
    float w0 = W[((size_t)r * CO + 2 * u) * I_N + i];
    float w1 = W[((size_t)r * CO + 2 * u + 1) * I_N + i];
    g_wh[idx] = __floats2half2_rn(w0, w1);
}

// ---------------------------------------------------------------------------
// K1: u_hat via HFMA2 (2 columns/thread) -> fp16 padded tiles, fused
// softmax(b_init) + fp32 s1 partials.
// grid = 16 b-tiles x 32 r-chunks = 512 blocks, 160 threads.
// ---------------------------------------------------------------------------
__global__ __launch_bounds__(160) void k1(const float* __restrict__ x,
                                          const float* __restrict__ binit) {
    const int bt = blockIdx.x & 15;
    const int rc = blockIdx.x >> 4;          // 0..31 (36-row chunk)
    const int b0 = bt * TB;
    const int tid = threadIdx.x;
    const int r0 = rc * K1_RC;
    const int chk_g = rc >> 1;               // 72-row tile id
    const int rin0 = (rc & 1) * K1_RC;       // row offset within tile

    const int grp = tid / 80;                // batch half
    const int u   = tid - grp * 80;          // column pair (cols 2u, 2u+1)
    const int c   = u >> 3;                  // capsule (same for both cols)
    const int bb0 = grp * 8;

    __shared__ __half2 x2_sm[TB][K1_RC][I_N];   // duplicated-lane x (32B rows)
    __shared__ float   c_sm[TB][K1_RC][C_N];    // routing coeffs

    const float4* x4 = reinterpret_cast<const float4*>(x);

    // stage x as duplicated half2 (one float4 -> four half2)
    for (int i = tid; i < TB * K1_RC * 2; i += 160) {
        int bb = i / (K1_RC * 2);
        int rem = i - bb * (K1_RC * 2);
        float4 v = x4[((size_t)(b0 + bb) * R_TOT + r0) * 2 + rem];
        __half2* dst = &x2_sm[bb][0][0] + rem * 4;
        dst[0] = __float2half2_rn(v.x);
        dst[1] = __float2half2_rn(v.y);
        dst[2] = __float2half2_rn(v.z);
        dst[3] = __float2half2_rn(v.w);
    }
    // softmax(b_init)
    for (int p = tid; p < TB * K1_RC; p += 160) {
        int bb = p / K1_RC;
        int rr = p - bb * K1_RC;
        const float* bp = binit + ((size_t)(b0 + bb) * R_TOT + r0 + rr) * C_N;
        float e[C_N];
        float m = bp[0];
#pragma unroll
        for (int j = 1; j < C_N; j++) m = fmaxf(m, bp[j]);
        float sum = 0.f;
#pragma unroll
        for (int j = 0; j < C_N; j++) { e[j] = expf(bp[j] - m); sum += e[j]; }
        float inv = 1.f / sum;
#pragma unroll
        for (int j = 0; j < C_N; j++) c_sm[bb][rr][j] = e[j] * inv;
    }
    __syncthreads();

    float2 s_acc[8];
#pragma unroll
    for (int i = 0; i < 8; i++) s_acc[i] = make_float2(0.f, 0.f);

    for (int rr = 0; rr < K1_RC; rr++) {
        const int r = r0 + rr;
        const int rin = rin0 + rr;
        __half2 w[8];
        {
            const uint4* wp = reinterpret_cast<const uint4*>(g_wh + ((size_t)r * 80 + u) * I_N);
            uint4 a = wp[0], bq = wp[1];
            w[0] = *reinterpret_cast<__half2*>(&a.x);
            w[1] = *reinterpret_cast<__half2*>(&a.y);
            w[2] = *reinterpret_cast<__half2*>(&a.z);
            w[3] = *reinterpret_cast<__half2*>(&a.w);
            w[4] = *reinterpret_cast<__half2*>(&bq.x);
            w[5] = *reinterpret_cast<__half2*>(&bq.y);
            w[6] = *reinterpret_cast<__half2*>(&bq.z);
            w[7] = *reinterpret_cast<__half2*>(&bq.w);
        }
#pragma unroll
        for (int bbl = 0; bbl < 8; bbl++) {
            const int bb = bb0 + bbl;
            const uint4* xq = reinterpret_cast<const uint4*>(&x2_sm[bb][rr][0]);
            uint4 xa = xq[0], xb = xq[1];
            __half2 x0 = *reinterpret_cast<__half2*>(&xa.x);
            __half2 x1 = *reinterpret_cast<__half2*>(&xa.y);
            __half2 x2 = *reinterpret_cast<__half2*>(&xa.z);
            __half2 x3 = *reinterpret_cast<__half2*>(&xa.w);
            __half2 x4h = *reinterpret_cast<__half2*>(&xb.x);
            __half2 x5 = *reinterpret_cast<__half2*>(&xb.y);
            __half2 x6 = *reinterpret_cast<__half2*>(&xb.z);
            __half2 x7 = *reinterpret_cast<__half2*>(&xb.w);
            __half2 acc = __hmul2(w[0], x0);
            acc = __hfma2(w[1], x1, acc);
            acc = __hfma2(w[2], x2, acc);
            acc = __hfma2(w[3], x3, acc);
            acc = __hfma2(w[4], x4h, acc);
            acc = __hfma2(w[5], x5, acc);
            acc = __hfma2(w[6], x6, acc);
            acc = __hfma2(w[7], x7, acc);
            __half2* dst = reinterpret_cast<__half2*>(
                g_uh + ((size_t)(b0 + bb) * NCH_R + chk_g) * TILE_H + (size_t)rin * PAD_H);
            dst[u] = acc;
            float2 f = __half22float2(acc);
            const float cf = c_sm[bb][rr][c];
            s_acc[bbl].x = fmaf(cf, f.x, s_acc[bbl].x);
            s_acc[bbl].y = fmaf(cf, f.y, s_acc[bbl].y);
        }
    }
#pragma unroll
    for (int bbl = 0; bbl < 8; bbl++) {
        float2* sp = reinterpret_cast<float2*>(
            g_spart1 + ((size_t)rc * B_TOT + (b0 + bb0 + bbl)) * CO);
        sp[u] = s_acc[bbl];
    }
}

// ---------------------------------------------------------------------------
// Fused routing pass (iter = 2 or 3): bulk-copy 24.2KB fp16 tile, overlap
// with v recompute; phase A uses LDS.128 tile reads, phase B half2 col-pair
// per thread with row split. Iter 3 last block per batch does final squash.
// grid = 256 b x 16 chunks = 4096 blocks, 160 threads, ~29KB SMEM.
// ---------------------------------------------------------------------------
__global__ __launch_bounds__(160) void kroute(const float* __restrict__ binit,
                                              float* __restrict__ out, int iter) {
    extern __shared__ __align__(16) char smem_raw[];
    __half* uh = reinterpret_cast<__half*>(smem_raw);             // TILE_H halves
    float* cT  = reinterpret_cast<float*>(smem_raw + TILE_BYTES); // [C_N][RCHK]
    float* vs  = cT + C_N * RCHK;                                 // CO
    float* sp  = vs + CO;                                         // [2][CO]
    __shared__ __align__(8) unsigned long long mbar;
    __shared__ int is_last;

    const int b   = blockIdx.x >> 4;
    const int chk = blockIdx.x & 15;
    const int tid = threadIdx.x;

    const uint32_t uh_s = smem_u32(uh);
    const uint32_t mb_s = smem_u32(&mbar);

    if (tid == 0) {
        asm volatile("mbarrier.init.shared.b64 [%0], 1;" :: "r"(mb_s) : "memory");
        asm volatile("mbarrier.arrive.expect_tx.shared.b64 _, [%0], %1;"
                     :: "r"(mb_s), "r"((uint32_t)TILE_BYTES) : "memory");
        const __half* src = g_uh + ((size_t)b * NCH_R + chk) * TILE_H;
        asm volatile("cp.async.bulk.shared::cta.global.mbarrier::complete_tx::bytes "
                     "[%0], [%1], %2, [%3];"
                     :: "r"(uh_s), "l"(src), "r"((uint32_t)TILE_BYTES), "r"(mb_s)
                     : "memory");
    }

    // Overlap with bulk copy: recompute v = squash(sum of prev partials).
    if (tid < CO) {
        float s = 0.f;
        if (iter == 2) {
#pragma unroll
            for (int p = 0; p < K1_PARTS; p++)
                s += g_spart1[((size_t)p * B_TOT + b) * CO + tid];
        } else {
#pragma unroll
            for (int p = 0; p < NCH_R; p++)
                s += g_spart2[0][((size_t)p * B_TOT + b) * CO + tid];
        }
        float n = s * s;
#pragma unroll
        for (int off = 8; off >= 1; off >>= 1)
            n += __shfl_xor_sync(0xffffffffu, n, off);
        float scale = (n / (1.f + n)) * rsqrtf(n + 1e-8f);
        vs[tid] = scale * s;
    }
    __syncthreads();

    // wait for bulk copy (phase 0)
    asm volatile(
        "{\n\t.reg .pred P;\n\t"
        "W_%=: mbarrier.try_wait.parity.shared.b64 P, [%0], 0;\n\t"
        "@!P bra W_%=;\n\t}"
        :: "r"(mb_s) : "memory");

    // Phase A: agreement + b update + softmax. 2 threads/row, 5 caps each;
    // tile reads via LDS.128 (row base 336B-aligned, cap block 32B offset).
    const unsigned mask = __ballot_sync(0xffffffffu, tid < 2 * RCHK);
    if (tid < 2 * RCHK) {
        const int row = tid >> 1;
        const int c0  = (tid & 1) * 5;
        const int r   = chk * RCHK + row;
        const float* bin = (iter == 2) ? (binit + ((size_t)b * R_TOT + r) * C_N)
                                       : (g_b2  + ((size_t)b * R_TOT + r) * C_N);
        float bv[5];
#pragma unroll
        for (int j = 0; j < 5; j++) {
            const int cc = c0 + j;
            const uint4* up = reinterpret_cast<const uint4*>(uh + row * PAD_H + cc * O_N);
            uint4 qa = up[0], qb = up[1];
            const float* vp = vs + cc * O_N;
            float a = 0.f;
            float2 f;
            f = __half22float2(*reinterpret_cast<__half2*>(&qa.x));
            a = fmaf(f.x, vp[0], a);  a = fmaf(f.y, vp[1], a);
            f = __half22float2(*reinterpret_cast<__half2*>(&qa.y));
            a = fmaf(f.x, vp[2], a);  a = fmaf(f.y, vp[3], a);
            f = __half22float2(*reinterpret_cast<__half2*>(&qa.z));
            a = fmaf(f.x, vp[4], a);  a = fmaf(f.y, vp[5], a);
            f = __half22float2(*reinterpret_cast<__half2*>(&qa.w));
            a = fmaf(f.x, vp[6], a);  a = fmaf(f.y, vp[7], a);
            f = __half22float2(*reinterpret_cast<__half2*>(&qb.x));
            a = fmaf(f.x, vp[8], a);  a = fmaf(f.y, vp[9], a);
            f = __half22float2(*reinterpret_cast<__half2*>(&qb.y));
            a = fmaf(f.x, vp[10], a); a = fmaf(f.y, vp[11], a);
            f = __half22float2(*reinterpret_cast<__half2*>(&qb.z));
            a = fmaf(f.x, vp[12], a); a = fmaf(f.y, vp[13], a);
            f = __half22float2(*reinterpret_cast<__half2*>(&qb.w));
            a = fmaf(f.x, vp[14], a); a = fmaf(f.y, vp[15], a);
            bv[j] = bin[cc] + a;
        }
        if (iter == 2) {  // persist b2 for iteration 3
            float* bo = g_b2 + ((size_t)b * R_TOT + r) * C_N;
#pragma unroll
            for (int j = 0; j < 5; j++) bo[c0 + j] = bv[j];
        }
        float m = bv[0];
#pragma unroll
        for (int j = 1; j < 5; j++) m = fmaxf(m, bv[j]);
        m = fmaxf(m, __shfl_xor_sync(mask, m, 1));
        float e[5], ps = 0.f;
#pragma unroll
        for (int j = 0; j < 5; j++) { e[j] = expf(bv[j] - m); ps += e[j]; }
        ps += __shfl_xor_sync(mask, ps, 1);
        const float inv = 1.f / ps;
#pragma unroll
        for (int j = 0; j < 5; j++) cT[(c0 + j) * RCHK + row] = e[j] * inv;
    }
    __syncthreads();

    // Phase B: s partial; thread = (col pair u, row half g): 36 half2 loads.
    {
        const int g = tid / 80;
        const int u = tid - g * 80;
        const int cc = u >> 3;                 // capsule of the pair
        const float* crow = cT + cc * RCHK + g * (RCHK / 2);
        const __half2* ucol = reinterpret_cast<const __half2*>(
            uh + (size_t)g * (RCHK / 2) * PAD_H) + u;
        float2 acc = make_float2(0.f, 0.f);
#pragma unroll 4
        for (int r = 0; r < RCHK / 2; r++) {
            float2 f = __half22float2(ucol[r * (PAD_H / 2)]);
            const float cf = crow[r];
            acc.x = fmaf(cf, f.x, acc.x);
            acc.y = fmaf(cf, f.y, acc.y);
        }
        reinterpret_cast<float2*>(sp + g * CO)[u] = acc;
    }
    __syncthreads();
    if (tid < CO) {
        const int slot = (iter == 2) ? 0 : 1;
        g_spart2[slot][((size_t)chk * B_TOT + b) * CO + tid] = sp[tid] + sp[CO + tid];
    }

    // Iter 3: last block per batch performs the final squash -> out.
    if (iter == 3) {
        __threadfence();
        __syncthreads();
        if (tid == 0) {
            int prev = atomicAdd(&g_cnt[b], 1);
            is_last = (prev == NCH_R - 1);
        }
        __syncthreads();
        if (is_last) {
            __threadfence();
            if (tid < CO) {
                float s = 0.f;
#pragma unroll
                for (int p = 0; p < NCH_R; p++)
                    s += g_spart2[1][((size_t)p * B_TOT + b) * CO + tid];
                float n = s * s;
#pragma unroll
                for (int off = 8; off >= 1; off >>= 1)
                    n += __shfl_xor_sync(0xffffffffu, n, off);
                float scale = (n / (1.f + n)) * rsqrtf(n + 1e-8f);
                out[(size_t)b * CO + tid] = scale * s;
            }
            if (tid == 0) g_cnt[b] = 0;   // reset for next graph replay
        }
    }
}

// ---------------------------------------------------------------------------
extern "C" void kernel_launch(void* const* d_in, const int* in_sizes, int n_in,
                              void* d_out, int out_size) {
    const float *x = nullptr, *W = nullptr, *binit = nullptr;
    for (int i = 0; i < n_in; i++) {
        if (in_sizes[i] == B_TOT * R_TOT * I_N)          x     = (const float*)d_in[i];
        else if (in_sizes[i] == R_TOT * C_N * O_N * I_N) W     = (const float*)d_in[i];
        else if (in_sizes[i] == B_TOT * R_TOT * C_N)     binit = (const float*)d_in[i];
    }
    float* out = (float*)d_out;

    const int SMEM_ROUTE = TILE_BYTES + (C_N * RCHK + CO + 2 * CO) * (int)sizeof(float);
    cudaFuncSetAttribute(kroute, cudaFuncAttributeMaxDynamicSharedMemorySize, SMEM_ROUTE);

    // pack W into fp16 column pairs
    k0<<<(R_TOT * 80 * I_N + 255) / 256, 256>>>(W);
    // iter 1: u_hat (fp16 HFMA2) + s1 partials
    k1<<<512, 160>>>(x, binit);
    // iter 2: v1 (in-block) + agreement + b2 + softmax + s2
    kroute<<<4096, 160, SMEM_ROUTE>>>(binit, out, 2);
    // iter 3: v2 (in-block) + agreement + softmax + s3 + fused final squash
    kroute<<<4096, 160, SMEM_ROUTE>>>(binit, out, 3);
}

// round 12
// speedup vs baseline: 1.4390x; 1.0378x over previous
#include <cuda_runtime.h>
#include <cuda_fp16.h>
#include <cstdint>

#define R_TOT 1152
#define B_TOT 256
#define C_N 10
#define O_N 16
#define CO 160
#define I_N 8

// kroute tiling
#define NCH_R 16           // route chunks per batch
#define RCHK 72            // rows per route chunk
#define PAD_H 168          // fp16 row stride: 336B rows, 16B-aligned for LDS.128
#define TILE_H (RCHK * PAD_H)          // 12096 halves
#define TILE_BYTES (TILE_H * 2)        // 24192 (16B multiple)

// k1 tiling
#define TB 16              // batches per k1 block
#define K1_RC 36           // rows per k1 block
#define K1_NCH 32          // 1152/36 r-chunks
#define K1_PARTS 32        // s1 partial chunks

// Scratch (device globals: allocation-free kernel_launch)
__device__ __half g_uh[(size_t)B_TOT * NCH_R * TILE_H];      // ~99 MB fp16
__device__ __half2 g_wh[(size_t)R_TOT * 80 * I_N];           // W packed column pairs
__device__ float  g_b2[(size_t)B_TOT * R_TOT * C_N];         // b after iter-1 update
__device__ float  g_spart1[(size_t)K1_PARTS * B_TOT * CO];   // k1 partial s
__device__ float  g_spart2[2][(size_t)NCH_R * B_TOT * CO];   // kroute partial s
__device__ int    g_cnt[B_TOT];                              // last-block counters

__device__ __forceinline__ uint32_t smem_u32(const void* p) {
    uint32_t a;
    asm("{ .reg .u64 t; cvta.to.shared.u64 t, %1; cvt.u32.u64 %0, t; }" : "=r"(a) : "l"(p));
    return a;
}
__device__ __forceinline__ __half2 u2h(uint32_t v) {
    return *reinterpret_cast<__half2*>(&v);
}

// ---------------------------------------------------------------------------
// K0: pack W (fp32 [R, CO, I]) into column-pair half2 layout [r][u][i].
// ---------------------------------------------------------------------------
__global__ __launch_bounds__(256) void k0(const float* __restrict__ W) {
    int idx = blockIdx.x * 256 + threadIdx.x;        // over R_TOT*80*8
    if (idx >= R_TOT * 80 * I_N) return;
    int i = idx & 7;
    int t = idx >> 3;
    int u = t % 80;
    int r = t / 80;
    float w0 = W[((size_t)r * CO + 2 * u) * I_N + i];
    float w1 = W[((size_t)r * CO + 2 * u + 1) * I_N + i];
    g_wh[idx] = __floats2half2_rn(w0, w1);
}

// ---------------------------------------------------------------------------
// K1: u_hat via HFMA2 (2 columns/thread) -> fp16 padded tiles, fused
// softmax(b_init) + fp32 s1 partials.
// grid = 16 b-tiles x 32 r-chunks = 512 blocks, 160 threads.
// ---------------------------------------------------------------------------
__global__ __launch_bounds__(160) void k1(const float* __restrict__ x,
                                          const float* __restrict__ binit) {
    const int bt = blockIdx.x & 15;
    const int rc = blockIdx.x >> 4;          // 0..31 (36-row chunk)
    const int b0 = bt * TB;
    const int tid = threadIdx.x;
    const int r0 = rc * K1_RC;
    const int chk_g = rc >> 1;               // 72-row tile id
    const int rin0 = (rc & 1) * K1_RC;       // row offset within tile

    const int grp = tid / 80;                // batch half
    const int u   = tid - grp * 80;          // column pair (cols 2u, 2u+1)
    const int c   = u >> 3;                  // capsule (same for both cols)
    const int bb0 = grp * 8;

    __shared__ __half2 x2_sm[TB][K1_RC][I_N];   // duplicated-lane x (32B rows)
    __shared__ float   c_sm[TB][K1_RC][C_N];    // routing coeffs

    const float4* x4 = reinterpret_cast<const float4*>(x);

    // stage x as duplicated half2 (one float4 -> four half2)
    for (int i = tid; i < TB * K1_RC * 2; i += 160) {
        int bb = i / (K1_RC * 2);
        int rem = i - bb * (K1_RC * 2);
        float4 v = x4[((size_t)(b0 + bb) * R_TOT + r0) * 2 + rem];
        __half2* dst = &x2_sm[bb][0][0] + rem * 4;
        dst[0] = __float2half2_rn(v.x);
        dst[1] = __float2half2_rn(v.y);
        dst[2] = __float2half2_rn(v.z);
        dst[3] = __float2half2_rn(v.w);
    }
    // softmax(b_init)
    for (int p = tid; p < TB * K1_RC; p += 160) {
        int bb = p / K1_RC;
        int rr = p - bb * K1_RC;
        const float* bp = binit + ((size_t)(b0 + bb) * R_TOT + r0 + rr) * C_N;
        float e[C_N];
        float m = bp[0];
#pragma unroll
        for (int j = 1; j < C_N; j++) m = fmaxf(m, bp[j]);
        float sum = 0.f;
#pragma unroll
        for (int j = 0; j < C_N; j++) { e[j] = __expf(bp[j] - m); sum += e[j]; }
        float inv = 1.f / sum;
#pragma unroll
        for (int j = 0; j < C_N; j++) c_sm[bb][rr][j] = e[j] * inv;
    }
    __syncthreads();

    float2 s_acc[8];
#pragma unroll
    for (int i = 0; i < 8; i++) s_acc[i] = make_float2(0.f, 0.f);

    for (int rr = 0; rr < K1_RC; rr++) {
        const int r = r0 + rr;
        const int rin = rin0 + rr;
        __half2 w[8];
        {
            const uint4* wp = reinterpret_cast<const uint4*>(g_wh + ((size_t)r * 80 + u) * I_N);
            uint4 a = wp[0], bq = wp[1];
            w[0] = u2h(a.x);  w[1] = u2h(a.y);  w[2] = u2h(a.z);  w[3] = u2h(a.w);
            w[4] = u2h(bq.x); w[5] = u2h(bq.y); w[6] = u2h(bq.z); w[7] = u2h(bq.w);
        }
#pragma unroll
        for (int bbl = 0; bbl < 8; bbl++) {
            const int bb = bb0 + bbl;
            const uint4* xq = reinterpret_cast<const uint4*>(&x2_sm[bb][rr][0]);
            uint4 xa = xq[0], xb = xq[1];
            __half2 acc = __hmul2(w[0], u2h(xa.x));
            acc = __hfma2(w[1], u2h(xa.y), acc);
            acc = __hfma2(w[2], u2h(xa.z), acc);
            acc = __hfma2(w[3], u2h(xa.w), acc);
            acc = __hfma2(w[4], u2h(xb.x), acc);
            acc = __hfma2(w[5], u2h(xb.y), acc);
            acc = __hfma2(w[6], u2h(xb.z), acc);
            acc = __hfma2(w[7], u2h(xb.w), acc);
            __half2* dst = reinterpret_cast<__half2*>(
                g_uh + ((size_t)(b0 + bb) * NCH_R + chk_g) * TILE_H + (size_t)rin * PAD_H);
            dst[u] = acc;
            float2 f = __half22float2(acc);
            const float cf = c_sm[bb][rr][c];
            s_acc[bbl].x = fmaf(cf, f.x, s_acc[bbl].x);
            s_acc[bbl].y = fmaf(cf, f.y, s_acc[bbl].y);
        }
    }
#pragma unroll
    for (int bbl = 0; bbl < 8; bbl++) {
        float2* sp = reinterpret_cast<float2*>(
            g_spart1 + ((size_t)rc * B_TOT + (b0 + bb0 + bbl)) * CO);
        sp[u] = s_acc[bbl];
    }
}

// ---------------------------------------------------------------------------
// Fused routing pass (iter = 2 or 3): bulk-copy 24.2KB fp16 tile, overlap
// with v recompute (v stored as half2 for phase A); phase A = HFMA2
// agreement, phase B = fp32 accumulation with float4 coeff loads.
// Iter 3 last block per batch does final squash. grid = 4096, 160 threads.
// ---------------------------------------------------------------------------
__global__ __launch_bounds__(160) void kroute(const float* __restrict__ binit,
                                              float* __restrict__ out, int iter) {
    extern __shared__ __align__(16) char smem_raw[];
    __half* uh = reinterpret_cast<__half*>(smem_raw);             // TILE_H halves
    float* cT  = reinterpret_cast<float*>(smem_raw + TILE_BYTES); // [C_N][RCHK]
    __half2* vsh = reinterpret_cast<__half2*>(cT + C_N * RCHK);   // 80 half2 (320B)
    float* sp  = reinterpret_cast<float*>(vsh + 80);              // [2][CO]
    __shared__ __align__(8) unsigned long long mbar;
    __shared__ int is_last;

    const int b   = blockIdx.x >> 4;
    const int chk = blockIdx.x & 15;
    const int tid = threadIdx.x;

    const uint32_t uh_s = smem_u32(uh);
    const uint32_t mb_s = smem_u32(&mbar);

    if (tid == 0) {
        asm volatile("mbarrier.init.shared.b64 [%0], 1;" :: "r"(mb_s) : "memory");
        asm volatile("mbarrier.arrive.expect_tx.shared.b64 _, [%0], %1;"
                     :: "r"(mb_s), "r"((uint32_t)TILE_BYTES) : "memory");
        const __half* src = g_uh + ((size_t)b * NCH_R + chk) * TILE_H;
        asm volatile("cp.async.bulk.shared::cta.global.mbarrier::complete_tx::bytes "
                     "[%0], [%1], %2, [%3];"
                     :: "r"(uh_s), "l"(src), "r"((uint32_t)TILE_BYTES), "r"(mb_s)
                     : "memory");
    }

    // Overlap with bulk copy: recompute v = squash(sum of prev partials);
    // store as half2 for phase A consumption.
    if (tid < CO) {
        float s = 0.f;
        if (iter == 2) {
#pragma unroll
            for (int p = 0; p < K1_PARTS; p++)
                s += g_spart1[((size_t)p * B_TOT + b) * CO + tid];
        } else {
#pragma unroll
            for (int p = 0; p < NCH_R; p++)
                s += g_spart2[0][((size_t)p * B_TOT + b) * CO + tid];
        }
        float n = s * s;
#pragma unroll
        for (int off = 8; off >= 1; off >>= 1)
            n += __shfl_xor_sync(0xffffffffu, n, off);
        float scale = (n / (1.f + n)) * rsqrtf(n + 1e-8f);
        float val = scale * s;
        float nb = __shfl_down_sync(0xffffffffu, val, 1);
        if (!(tid & 1)) vsh[tid >> 1] = __floats2half2_rn(val, nb);
    }
    __syncthreads();

    // wait for bulk copy (phase 0)
    asm volatile(
        "{\n\t.reg .pred P;\n\t"
        "W_%=: mbarrier.try_wait.parity.shared.b64 P, [%0], 0;\n\t"
        "@!P bra W_%=;\n\t}"
        :: "r"(mb_s) : "memory");

    // Phase A: agreement via HFMA2 + b update + softmax. 2 threads/row.
    const unsigned mask = __ballot_sync(0xffffffffu, tid < 2 * RCHK);
    if (tid < 2 * RCHK) {
        const int row = tid >> 1;
        const int c0  = (tid & 1) * 5;
        const int r   = chk * RCHK + row;
        const float* bin = (iter == 2) ? (binit + ((size_t)b * R_TOT + r) * C_N)
                                       : (g_b2  + ((size_t)b * R_TOT + r) * C_N);
        float bv[5];
#pragma unroll
        for (int j = 0; j < 5; j++) {
            const int cc = c0 + j;
            const uint4* up = reinterpret_cast<const uint4*>(uh + row * PAD_H + cc * O_N);
            uint4 qa = up[0], qb = up[1];
            const uint4* vp = reinterpret_cast<const uint4*>(vsh + cc * 8);
            uint4 va = vp[0], vb = vp[1];
            __half2 acc = __hmul2(u2h(qa.x), u2h(va.x));
            acc = __hfma2(u2h(qa.y), u2h(va.y), acc);
            acc = __hfma2(u2h(qa.z), u2h(va.z), acc);
            acc = __hfma2(u2h(qa.w), u2h(va.w), acc);
            acc = __hfma2(u2h(qb.x), u2h(vb.x), acc);
            acc = __hfma2(u2h(qb.y), u2h(vb.y), acc);
            acc = __hfma2(u2h(qb.z), u2h(vb.z), acc);
            acc = __hfma2(u2h(qb.w), u2h(vb.w), acc);
            float2 fa = __half22float2(acc);
            bv[j] = bin[cc] + fa.x + fa.y;
        }
        if (iter == 2) {  // persist b2 for iteration 3
            float* bo = g_b2 + ((size_t)b * R_TOT + r) * C_N;
#pragma unroll
            for (int j = 0; j < 5; j++) bo[c0 + j] = bv[j];
        }
        float m = bv[0];
#pragma unroll
        for (int j = 1; j < 5; j++) m = fmaxf(m, bv[j]);
        m = fmaxf(m, __shfl_xor_sync(mask, m, 1));
        float e[5], ps = 0.f;
#pragma unroll
        for (int j = 0; j < 5; j++) { e[j] = __expf(bv[j] - m); ps += e[j]; }
        ps += __shfl_xor_sync(mask, ps, 1);
        const float inv = 1.f / ps;
#pragma unroll
        for (int j = 0; j < 5; j++) cT[(c0 + j) * RCHK + row] = e[j] * inv;
    }
    __syncthreads();

    // Phase B: s partial (fp32); thread = (col pair u, row half g).
    {
        const int g = tid / 80;
        const int u = tid - g * 80;
        const int cc = u >> 3;                 // capsule of the pair
        const float4* crow = reinterpret_cast<const float4*>(cT + cc * RCHK + g * 36);
        const __half2* ucol = reinterpret_cast<const __half2*>(
            uh + (size_t)g * 36 * PAD_H) + u;
        float2 acc = make_float2(0.f, 0.f);
#pragma unroll
        for (int r4 = 0; r4 < 9; r4++) {
            float4 cf = crow[r4];
            float2 f;
            f = __half22float2(ucol[(r4 * 4 + 0) * (PAD_H / 2)]);
            acc.x = fmaf(cf.x, f.x, acc.x); acc.y = fmaf(cf.x, f.y, acc.y);
            f = __half22float2(ucol[(r4 * 4 + 1) * (PAD_H / 2)]);
            acc.x = fmaf(cf.y, f.x, acc.x); acc.y = fmaf(cf.y, f.y, acc.y);
            f = __half22float2(ucol[(r4 * 4 + 2) * (PAD_H / 2)]);
            acc.x = fmaf(cf.z, f.x, acc.x); acc.y = fmaf(cf.z, f.y, acc.y);
            f = __half22float2(ucol[(r4 * 4 + 3) * (PAD_H / 2)]);
            acc.x = fmaf(cf.w, f.x, acc.x); acc.y = fmaf(cf.w, f.y, acc.y);
        }
        reinterpret_cast<float2*>(sp + g * CO)[u] = acc;
    }
    __syncthreads();
    if (tid < CO) {
        const int slot = (iter == 2) ? 0 : 1;
        g_spart2[slot][((size_t)chk * B_TOT + b) * CO + tid] = sp[tid] + sp[CO + tid];
    }

    // Iter 3: last block per batch performs the final squash -> out.
    if (iter == 3) {
        __threadfence();
        __syncthreads();
        if (tid == 0) {
            int prev = atomicAdd(&g_cnt[b], 1);
            is_last = (prev == NCH_R - 1);
        }
        __syncthreads();
        if (is_last) {
            __threadfence();
            if (tid < CO) {
                float s = 0.f;
#pragma unroll
                for (int p = 0; p < NCH_R; p++)
                    s += g_spart2[1][((size_t)p * B_TOT + b) * CO + tid];
                float n = s * s;
#pragma unroll
                for (int off = 8; off >= 1; off >>= 1)
                    n += __shfl_xor_sync(0xffffffffu, n, off);
                float scale = (n / (1.f + n)) * rsqrtf(n + 1e-8f);
                out[(size_t)b * CO + tid] = scale * s;
            }
            if (tid == 0) g_cnt[b] = 0;   // reset for next graph replay
        }
    }
}

// ---------------------------------------------------------------------------
extern "C" void kernel_launch(void* const* d_in, const int* in_sizes, int n_in,
                              void* d_out, int out_size) {
    const float *x = nullptr, *W = nullptr, *binit = nullptr;
    for (int i = 0; i < n_in; i++) {
        if (in_sizes[i] == B_TOT * R_TOT * I_N)          x     = (const float*)d_in[i];
        else if (in_sizes[i] == R_TOT * C_N * O_N * I_N) W     = (const float*)d_in[i];
        else if (in_sizes[i] == B_TOT * R_TOT * C_N)     binit = (const float*)d_in[i];
    }
    float* out = (float*)d_out;

    const int SMEM_ROUTE = TILE_BYTES +
        (C_N * RCHK) * (int)sizeof(float) + 80 * 4 + 2 * CO * (int)sizeof(float);
    cudaFuncSetAttribute(kroute, cudaFuncAttributeMaxDynamicSharedMemorySize, SMEM_ROUTE);

    // pack W into fp16 column pairs
    k0<<<(R_TOT * 80 * I_N + 255) / 256, 256>>>(W);
    // iter 1: u_hat (fp16 HFMA2) + s1 partials
    k1<<<512, 160>>>(x, binit);
    // iter 2: v1 (in-block) + agreement + b2 + softmax + s2
    kroute<<<4096, 160, SMEM_ROUTE>>>(binit, out, 2);
    // iter 3: v2 (in-block) + agreement + softmax + s3 + fused final squash
    kroute<<<4096, 160, SMEM_ROUTE>>>(binit, out, 3);
}